// round 2
// baseline (speedup 1.0000x reference)
#include <cuda_runtime.h>

#define HH 128
#define WW 256
#define SS 12
#define CC 32
#define TEMP 7.0f
#define RB 8     // output rows per block
#define LR 12    // smem rows = RB + 4 halo (2 each side)

// Pass-invariant dot table: dot[h][w][x] = sum_c left[c,h,w] * right[c,h,x]
// Only the band x in [w-80, w+15] is computed; passes read x in [w-72, w+1].
__device__ float g_tab[HH * WW * WW];   // 33.5 MB, L2-resident

// ---------------------------------------------------------------------------
// Table build: per (row, half-row) block, register-tiled 8x8 FFMA GEMM over
// the disparity band. 192 threads = 16 w-tiles x 12 x-tiles.
// ---------------------------------------------------------------------------
__global__ __launch_bounds__(192) void build_table_kernel(
    const float* __restrict__ left, const float* __restrict__ right) {
    __shared__ float As[CC][128];
    __shared__ float Rs[CC][WW];

    const int h = blockIdx.y;
    const int wbase = blockIdx.x * 128;
    const int tid = threadIdx.x;

    for (int i = tid; i < CC * 128; i += 192) {
        int c = i >> 7, wl = i & 127;
        As[c][wl] = left[(c * HH + h) * WW + wbase + wl];
    }
    for (int i = tid; i < CC * WW; i += 192) {
        int c = i >> 8, x = i & 255;
        Rs[c][x] = right[(c * HH + h) * WW + x];
    }
    __syncthreads();

    const int tw = tid / 12;            // w-tile within half-row: 0..15
    const int j  = tid % 12;            // band x-tile offset: 0..11
    const int twg = (wbase >> 3) + tw;  // global w-tile 0..31
    const int txg = twg - 10 + j;       // x-tiles [twg-10, twg+1]
    if (txg < 0 || txg > 31) return;

    const int wl = tw * 8;
    const int x  = txg * 8;

    float acc[8][8];
    #pragma unroll
    for (int i = 0; i < 8; i++)
        #pragma unroll
        for (int q = 0; q < 8; q++) acc[i][q] = 0.0f;

    #pragma unroll 8
    for (int k = 0; k < CC; k++) {
        float a[8], b[8];
        *(float4*)&a[0] = *(const float4*)&As[k][wl];
        *(float4*)&a[4] = *(const float4*)&As[k][wl + 4];
        *(float4*)&b[0] = *(const float4*)&Rs[k][x];
        *(float4*)&b[4] = *(const float4*)&Rs[k][x + 4];
        #pragma unroll
        for (int i = 0; i < 8; i++)
            #pragma unroll
            for (int q = 0; q < 8; q++)
                acc[i][q] += a[i] * b[q];
    }

    float* dst = g_tab + ((size_t)(h * WW + wbase + wl)) * WW + x;
    #pragma unroll
    for (int i = 0; i < 8; i++) {
        float4 s0 = make_float4(acc[i][0], acc[i][1], acc[i][2], acc[i][3]);
        float4 s1 = make_float4(acc[i][4], acc[i][5], acc[i][6], acc[i][7]);
        *(float4*)(dst + (size_t)i * WW)     = s0;
        *(float4*)(dst + (size_t)i * WW + 4) = s1;
    }
}

// ---------------------------------------------------------------------------
// Per-pixel evaluation: 3 taps -> 3 bilinear table lookups -> softmax.
// ---------------------------------------------------------------------------
__device__ __forceinline__ void eval_px(
    float np0, float np1, float np2, float im, float sv,
    const float* __restrict__ tabrow, int w,
    float& nout, float& dout) {
    float np[3] = {np0, np1, np2};
    float cost[3], dsv[3];
    #pragma unroll
    for (int c = 0; c < 3; c++) {
        float disp = fmaf(np[c], sv, im);
        dsv[c] = disp;
        float xs = (float)w - disp;
        float x0f = floorf(xs);
        float frac = xs - x0f;
        int x0 = (int)x0f;
        int x1 = x0 + 1;
        // Predicated reads so uninitialized band slots can't inject NaN.
        float d0 = (x0 >= 0 && x0 < WW) ? __ldg(tabrow + x0) : 0.0f;
        float d1 = (x1 >= 0 && x1 < WW) ? __ldg(tabrow + x1) : 0.0f;
        cost[c] = (d0 * (1.0f - frac) + d1 * frac) * (TEMP / (float)CC);
    }
    float m = fmaxf(cost[0], fmaxf(cost[1], cost[2]));
    float e0 = __expf(cost[0] - m);
    float e1 = __expf(cost[1] - m);
    float e2 = __expf(cost[2] - m);
    float rZ = 1.0f / (e0 + e1 + e2);
    nout = (e0 * np[0]  + e1 * np[1]  + e2 * np[2])  * rZ;
    dout = (e0 * dsv[0] + e1 * dsv[1] + e2 * dsv[2]) * rZ;
}

// ---------------------------------------------------------------------------
// Fully fused 4-pass PatchMatch. grid = (S, H/RB), block = 1024.
// Each block: 8 output rows + 2 halo rows each side, noise ping-pongs in smem.
// Passes: 0=H rows[0,12), 1=V rows[1,11), 2=H rows[1,11), 3=V rows[2,10)->out.
// ---------------------------------------------------------------------------
__global__ __launch_bounds__(1024) void pm_fused_kernel(
    const float* __restrict__ minD, const float* __restrict__ maxD,
    const float* __restrict__ ext_noise, float* __restrict__ disp_out) {
    __shared__ float snA[LR][WW];
    __shared__ float snB[LR][WW];
    __shared__ float sim[LR][WW];   // interval_min for this s
    __shared__ float ssv[LR][WW];   // search * interval

    const int s = blockIdx.x;
    const int hbase = blockIdx.y * RB;
    const int tid = threadIdx.x;
    const int w  = tid & (WW - 1);
    const int ty = tid >> 8;        // 0..3

    const float inv = 1.0f / (float)(SS + 1);

    // ---- init: load noise + per-pixel disparity interval ----
    for (int l = ty; l < LR; l += 4) {
        int h = hbase + l - 2;
        if (h >= 0 && h < HH) {
            int pix = h * WW + w;
            float md = fmaxf(minD[pix], 0.0f);
            float Md = fmaxf(maxD[pix], 0.0f);
            float search = Md - md;
            sim[l][w] = md + search * ((float)(s + 1) * inv);
            ssv[l][w] = search * inv;
            snA[l][w] = ext_noise[s * HH * WW + pix];
        } else {
            sim[l][w] = 0.0f; ssv[l][w] = 0.0f; snA[l][w] = 0.0f;
        }
    }
    __syncthreads();

    float nn, dd;

    // ---- pass 0: horizontal, rows [0,12), snA -> snB ----
    for (int l = ty; l < LR; l += 4) {
        int h = hbase + l - 2;
        if (h >= 0 && h < HH) {
            float n0 = (w >= 1)      ? snA[l][w - 1] : 0.0f;
            float n1 = snA[l][w];
            float n2 = (w < WW - 1)  ? snA[l][w + 1] : 0.0f;
            const float* tr = g_tab + (size_t)(h * WW + w) * WW;
            eval_px(n0, n1, n2, sim[l][w], ssv[l][w], tr, w, nn, dd);
            snB[l][w] = nn;
        }
    }
    __syncthreads();

    // ---- pass 1: vertical, rows [1,11), snB -> snA ----
    for (int l = 1 + ty; l < LR - 1; l += 4) {
        int h = hbase + l - 2;
        if (h >= 0 && h < HH) {
            float n0 = (h >= 1)      ? snB[l - 1][w] : 0.0f;
            float n1 = snB[l][w];
            float n2 = (h < HH - 1)  ? snB[l + 1][w] : 0.0f;
            const float* tr = g_tab + (size_t)(h * WW + w) * WW;
            eval_px(n0, n1, n2, sim[l][w], ssv[l][w], tr, w, nn, dd);
            snA[l][w] = nn;
        }
    }
    __syncthreads();

    // ---- pass 2: horizontal, rows [1,11), snA -> snB ----
    for (int l = 1 + ty; l < LR - 1; l += 4) {
        int h = hbase + l - 2;
        if (h >= 0 && h < HH) {
            float n0 = (w >= 1)      ? snA[l][w - 1] : 0.0f;
            float n1 = snA[l][w];
            float n2 = (w < WW - 1)  ? snA[l][w + 1] : 0.0f;
            const float* tr = g_tab + (size_t)(h * WW + w) * WW;
            eval_px(n0, n1, n2, sim[l][w], ssv[l][w], tr, w, nn, dd);
            snB[l][w] = nn;
        }
    }
    __syncthreads();

    // ---- pass 3: vertical, rows [2,10) -> final disp ----
    for (int l = 2 + ty; l < LR - 2; l += 4) {
        int h = hbase + l - 2;   // always valid: [hbase, hbase+RB)
        float n0 = (h >= 1)      ? snB[l - 1][w] : 0.0f;
        float n1 = snB[l][w];
        float n2 = (h < HH - 1)  ? snB[l + 1][w] : 0.0f;
        const float* tr = g_tab + (size_t)(h * WW + w) * WW;
        eval_px(n0, n1, n2, sim[l][w], ssv[l][w], tr, w, nn, dd);
        disp_out[s * HH * WW + h * WW + w] = dd;
    }
}

extern "C" void kernel_launch(void* const* d_in, const int* in_sizes, int n_in,
                              void* d_out, int out_size) {
    const float* left  = (const float*)d_in[0];
    const float* right = (const float*)d_in[1];
    const float* minD  = (const float*)d_in[2];
    const float* maxD  = (const float*)d_in[3];
    const float* noise = (const float*)d_in[4];
    float* disp = (float*)d_out;

    build_table_kernel<<<dim3(2, HH), 192>>>(left, right);
    pm_fused_kernel<<<dim3(SS, HH / RB), 1024>>>(minD, maxD, noise, disp);
}

// round 3
// speedup vs baseline: 1.1879x; 1.1879x over previous
#include <cuda_runtime.h>

#define HH 128
#define WW 256
#define SS 12
#define CC 32
#define BAND 74
#define HW (HH * WW)

// Stage 1 output: full-layout dot table dot[h][w][x] (band region only valid)
__device__ float g_tab[HH * WW * WW];            // 33.5 MB
// Stage 2 output: band-compacted transposed table [h][b][w], x = w+1-b
__device__ float g_bandt[HH * BAND * WW];        // 9.7 MB
__device__ float g_noiseA[SS * HW];
__device__ float g_noiseB[SS * HW];

// ---------------------------------------------------------------------------
// Stage 1: per (row, half-row) register-tiled 8x8 FFMA GEMM over the band.
// ---------------------------------------------------------------------------
__global__ __launch_bounds__(192) void build_table_kernel(
    const float* __restrict__ left, const float* __restrict__ right) {
    __shared__ float As[CC][128];
    __shared__ float Rs[CC][WW];

    const int h = blockIdx.y;
    const int wbase = blockIdx.x * 128;
    const int tid = threadIdx.x;

    for (int i = tid; i < CC * 128; i += 192) {
        int c = i >> 7, wl = i & 127;
        As[c][wl] = left[(c * HH + h) * WW + wbase + wl];
    }
    for (int i = tid; i < CC * WW; i += 192) {
        int c = i >> 8, x = i & 255;
        Rs[c][x] = right[(c * HH + h) * WW + x];
    }
    __syncthreads();

    const int tw = tid / 12;            // w-tile within half-row: 0..15
    const int j  = tid % 12;            // band x-tile offset: 0..11
    const int twg = (wbase >> 3) + tw;
    const int txg = twg - 10 + j;       // x-tiles [twg-10, twg+1]
    if (txg < 0 || txg > 31) return;

    const int wl = tw * 8;
    const int x  = txg * 8;

    float acc[8][8];
    #pragma unroll
    for (int i = 0; i < 8; i++)
        #pragma unroll
        for (int q = 0; q < 8; q++) acc[i][q] = 0.0f;

    #pragma unroll 8
    for (int k = 0; k < CC; k++) {
        float a[8], b[8];
        *(float4*)&a[0] = *(const float4*)&As[k][wl];
        *(float4*)&a[4] = *(const float4*)&As[k][wl + 4];
        *(float4*)&b[0] = *(const float4*)&Rs[k][x];
        *(float4*)&b[4] = *(const float4*)&Rs[k][x + 4];
        #pragma unroll
        for (int i = 0; i < 8; i++)
            #pragma unroll
            for (int q = 0; q < 8; q++)
                acc[i][q] += a[i] * b[q];
    }

    float* dst = g_tab + ((size_t)(h * WW + wbase + wl)) * WW + x;
    #pragma unroll
    for (int i = 0; i < 8; i++) {
        float4 s0 = make_float4(acc[i][0], acc[i][1], acc[i][2], acc[i][3]);
        float4 s1 = make_float4(acc[i][4], acc[i][5], acc[i][6], acc[i][7]);
        *(float4*)(dst + (size_t)i * WW)     = s0;
        *(float4*)(dst + (size_t)i * WW + 4) = s1;
    }
}

// ---------------------------------------------------------------------------
// Stage 2: shifted transpose g_tab[h][w][x] -> g_bandt[h][b][w], b = w+1-x.
// Block: (w-tile of 64, h). Coalesced load of [64 w][144 x] via smem, then
// coalesced write of each b-row (diagonal extraction, conflict-free reads).
// ---------------------------------------------------------------------------
__global__ __launch_bounds__(256) void transpose_band_kernel() {
    __shared__ float s[64][148];        // pad 148: 16B-aligned rows, cf reads
    const int h = blockIdx.y;
    const int w0 = blockIdx.x * 64;
    const int x0b = w0 - 76;            // covers x in [w0-76, w0+68)
    const int tid = threadIdx.x;

    for (int idx = tid; idx < 64 * 36; idx += 256) {
        int r = idx / 36, c4 = (idx % 36) * 4;
        int x = x0b + c4;
        const float* src = g_tab + ((size_t)(h * WW + w0 + r)) * WW;
        float4 v;
        if (x >= 0 && x + 3 < WW) {
            v = *(const float4*)(src + x);
        } else {
            v.x = (x + 0 >= 0 && x + 0 < WW) ? src[x + 0] : 0.0f;
            v.y = (x + 1 >= 0 && x + 1 < WW) ? src[x + 1] : 0.0f;
            v.z = (x + 2 >= 0 && x + 2 < WW) ? src[x + 2] : 0.0f;
            v.w = (x + 3 >= 0 && x + 3 < WW) ? src[x + 3] : 0.0f;
        }
        *(float4*)&s[r][c4] = v;
    }
    __syncthreads();

    const int tx = tid & 63;            // w offset
    const int ty = tid >> 6;            // b stride group
    // g_bandt[h][b][w0+tx] = g_tab[h][w0+tx][w0+tx+1-b] = s[tx][tx + 77 - b]
    for (int b = ty; b < BAND; b += 4) {
        g_bandt[((size_t)h * BAND + b) * WW + w0 + tx] = s[tx][tx + 77 - b];
    }
}

// ---------------------------------------------------------------------------
// One PatchMatch pass. Block = 64 pixels x all 12 samples; the 64-pixel band
// slice lives in smem with layout [b][w] -> conflict-free LDS gathers.
// grid = (W/64, H), block = 256 (64 w x 4 sample-groups of 3).
// ---------------------------------------------------------------------------
__global__ __launch_bounds__(256) void pm_pass_kernel(
    const float* __restrict__ minD, const float* __restrict__ maxD,
    const float* __restrict__ ext_noise, float* __restrict__ disp_out,
    int pass) {
    __shared__ float band[BAND][64];    // bank = w%32: conflict-free

    const int h = blockIdx.y;
    const int w0 = blockIdx.x * 64;
    const int tid = threadIdx.x;

    // Coalesced copy of this block's band slice (74 x 64 floats = 18.9 KB)
    for (int idx = tid; idx < BAND * 16; idx += 256) {
        int b = idx >> 4, c4 = (idx & 15) * 4;
        *(float4*)&band[b][c4] =
            *(const float4*)(g_bandt + ((size_t)h * BAND + b) * WW + w0 + c4);
    }
    __syncthreads();

    const int wl = tid & 63;
    const int sg = tid >> 6;            // 0..3, each handles 3 samples
    const int w = w0 + wl;
    const int pix = h * WW + w;

    const float* nin = (pass == 0) ? ext_noise
                                   : ((pass & 1) ? g_noiseA : g_noiseB);
    float* nout = (pass & 1) ? g_noiseB : g_noiseA;
    const bool horiz = ((pass & 1) == 0);

    const float md = fmaxf(minD[pix], 0.0f);
    const float Md = fmaxf(maxD[pix], 0.0f);
    const float search = Md - md;
    const float inv = 1.0f / (float)(SS + 1);
    const float sv = search * inv;

    #pragma unroll
    for (int k = 0; k < 3; k++) {
        const int s = sg * 3 + k;
        const float* ns = nin + s * HW;
        float np[3];
        np[1] = ns[pix];
        if (horiz) {
            np[0] = (w > 0)      ? ns[pix - 1]  : 0.0f;
            np[2] = (w < WW - 1) ? ns[pix + 1]  : 0.0f;
        } else {
            np[0] = (h > 0)      ? ns[pix - WW] : 0.0f;
            np[2] = (h < HH - 1) ? ns[pix + WW] : 0.0f;
        }
        const float im = md + search * ((float)(s + 1) * inv);

        float cost[3], dsv[3];
        #pragma unroll
        for (int c = 0; c < 3; c++) {
            float disp = im + np[c] * sv;
            dsv[c] = disp;
            float xs = (float)w - disp;
            float x0f = floorf(xs);
            float frac = xs - x0f;
            int x0 = (int)x0f;
            int x1 = x0 + 1;
            int b0 = w + 1 - x0;
            b0 = max(1, min(b0, BAND - 1));     // safety clamp (no-op in range)
            float d0 = (x0 >= 0)             ? band[b0][wl]     : 0.0f;
            float d1 = (x1 >= 0 && x1 < WW)  ? band[b0 - 1][wl] : 0.0f;
            cost[c] = (d0 * (1.0f - frac) + d1 * frac) * (7.0f / 32.0f);
        }

        float m = fmaxf(cost[0], fmaxf(cost[1], cost[2]));
        float e0 = __expf(cost[0] - m);
        float e1 = __expf(cost[1] - m);
        float e2 = __expf(cost[2] - m);
        float rZ = 1.0f / (e0 + e1 + e2);

        nout[s * HW + pix] = (e0 * np[0]  + e1 * np[1]  + e2 * np[2])  * rZ;
        if (pass == 3)
            disp_out[s * HW + pix] = (e0 * dsv[0] + e1 * dsv[1] + e2 * dsv[2]) * rZ;
    }
}

extern "C" void kernel_launch(void* const* d_in, const int* in_sizes, int n_in,
                              void* d_out, int out_size) {
    const float* left  = (const float*)d_in[0];
    const float* right = (const float*)d_in[1];
    const float* minD  = (const float*)d_in[2];
    const float* maxD  = (const float*)d_in[3];
    const float* noise = (const float*)d_in[4];
    float* disp = (float*)d_out;

    build_table_kernel<<<dim3(2, HH), 192>>>(left, right);
    transpose_band_kernel<<<dim3(4, HH), 256>>>();
    for (int p = 0; p < 4; p++) {
        pm_pass_kernel<<<dim3(4, HH), 256>>>(minD, maxD, noise, disp, p);
    }
}

// round 4
// speedup vs baseline: 1.2104x; 1.0189x over previous
#include <cuda_runtime.h>

#define HH 128
#define WW 256
#define SS 12
#define CC 32
#define BAND 74
#define HW (HH * WW)

// Stage 1: full-layout dot table dot[h][w][x] (band region only valid)
__device__ float g_tab[HH * WW * WW];            // 33.5 MB
// Stage 2: band-compacted transposed table [h][b][w], x = w+1-b
__device__ float g_bandt[HH * BAND * WW];        // 9.7 MB
__device__ float g_noiseA[SS * HW];
__device__ float g_noiseB[SS * HW];

#define FMA2(d, a, b, c) \
    asm("fma.rn.f32x2 %0, %1, %2, %3;" : "=l"(d) : "l"(a), "l"(b), "l"(c))
#define PACK2(out, v) \
    asm("mov.b64 %0, {%1, %1};" : "=l"(out) : "r"(__float_as_uint(v)))

// ---------------------------------------------------------------------------
// Stage 1: per (row, half-row) register-tiled 8x8 GEMM over the band,
// using packed f32x2 FMA (2x fp32 rate). 192 threads = 16 w-tiles x 12 slots
// (11 band x-tiles used).
// ---------------------------------------------------------------------------
__global__ __launch_bounds__(192) void build_table_kernel(
    const float* __restrict__ left, const float* __restrict__ right) {
    __shared__ float As[CC][128];
    __shared__ float Rs[CC][WW];

    const int h = blockIdx.y;
    const int wbase = blockIdx.x * 128;
    const int tid = threadIdx.x;

    for (int i = tid; i < CC * 128; i += 192) {
        int c = i >> 7, wl = i & 127;
        As[c][wl] = left[(c * HH + h) * WW + wbase + wl];
    }
    for (int i = tid; i < CC * WW; i += 192) {
        int c = i >> 8, x = i & 255;
        Rs[c][x] = right[(c * HH + h) * WW + x];
    }
    __syncthreads();

    const int tw = tid / 12;            // w-tile within half-row: 0..15
    const int j  = tid % 12;            // band x-tile slot: 0..11 (11 unused)
    const int twg = (wbase >> 3) + tw;
    const int txg = twg - 9 + j;        // needed x-tiles: [twg-9, twg+1]
    if (j >= 11 || txg < 0 || txg > 31) return;

    const int wl = tw * 8;
    const int x  = txg * 8;

    unsigned long long acc2[8][4];      // pairs along x: (q, q+1)
    #pragma unroll
    for (int i = 0; i < 8; i++)
        #pragma unroll
        for (int q = 0; q < 4; q++) acc2[i][q] = 0ULL;

    #pragma unroll 8
    for (int k = 0; k < CC; k++) {
        float a[8];
        *(float4*)&a[0] = *(const float4*)&As[k][wl];
        *(float4*)&a[4] = *(const float4*)&As[k][wl + 4];
        ulonglong2 t0 = *(const ulonglong2*)&Rs[k][x];
        ulonglong2 t1 = *(const ulonglong2*)&Rs[k][x + 4];
        unsigned long long b2[4] = {t0.x, t0.y, t1.x, t1.y};
        #pragma unroll
        for (int i = 0; i < 8; i++) {
            unsigned long long a2;
            PACK2(a2, a[i]);
            #pragma unroll
            for (int q = 0; q < 4; q++)
                FMA2(acc2[i][q], a2, b2[q], acc2[i][q]);
        }
    }

    float* dst = g_tab + ((size_t)(h * WW + wbase + wl)) * WW + x;
    #pragma unroll
    for (int i = 0; i < 8; i++) {
        ulonglong2* p = (ulonglong2*)(dst + (size_t)i * WW);
        p[0] = make_ulonglong2(acc2[i][0], acc2[i][1]);
        p[1] = make_ulonglong2(acc2[i][2], acc2[i][3]);
    }
}

// ---------------------------------------------------------------------------
// Stage 2: shifted transpose g_tab[h][w][x] -> g_bandt[h][b][w], b = w+1-x.
// Out-of-image x is zero-filled, so pass kernels need no boundary predicates.
// ---------------------------------------------------------------------------
__global__ __launch_bounds__(256) void transpose_band_kernel() {
    __shared__ float s[64][148];
    const int h = blockIdx.y;
    const int w0 = blockIdx.x * 64;
    const int x0b = w0 - 76;
    const int tid = threadIdx.x;

    for (int idx = tid; idx < 64 * 36; idx += 256) {
        int r = idx / 36, c4 = (idx % 36) * 4;
        int x = x0b + c4;
        const float* src = g_tab + ((size_t)(h * WW + w0 + r)) * WW;
        float4 v;
        if (x >= 0 && x + 3 < WW) {
            v = *(const float4*)(src + x);
        } else {
            v.x = (x + 0 >= 0 && x + 0 < WW) ? src[x + 0] : 0.0f;
            v.y = (x + 1 >= 0 && x + 1 < WW) ? src[x + 1] : 0.0f;
            v.z = (x + 2 >= 0 && x + 2 < WW) ? src[x + 2] : 0.0f;
            v.w = (x + 3 >= 0 && x + 3 < WW) ? src[x + 3] : 0.0f;
        }
        *(float4*)&s[r][c4] = v;
    }
    __syncthreads();

    const int tx = tid & 63;
    const int ty = tid >> 6;
    for (int b = ty; b < BAND; b += 4) {
        g_bandt[((size_t)h * BAND + b) * WW + w0 + tx] = s[tx][tx + 77 - b];
    }
}

// ---------------------------------------------------------------------------
// One PatchMatch pass. Thread = (pixel, sample); 4 samples share a block so
// the 64-wide band slice is L1-reused. No smem, no barriers, 1536 blocks.
// grid = (W/64, H, S/4), block = 256.
// ---------------------------------------------------------------------------
__global__ __launch_bounds__(256) void pm_pass_kernel(
    const float* __restrict__ minD, const float* __restrict__ maxD,
    const float* __restrict__ ext_noise, float* __restrict__ disp_out,
    int pass) {
    const int wl = threadIdx.x & 63;
    const int w  = blockIdx.x * 64 + wl;
    const int h  = blockIdx.y;
    const int s  = blockIdx.z * 4 + (threadIdx.x >> 6);
    const int pix = h * WW + w;

    const float* nin = (pass == 0) ? ext_noise
                                   : ((pass & 1) ? g_noiseA : g_noiseB);
    float* nout = (pass & 1) ? g_noiseB : g_noiseA;
    const bool horiz = ((pass & 1) == 0);

    const float md = fmaxf(__ldg(minD + pix), 0.0f);
    const float Md = fmaxf(__ldg(maxD + pix), 0.0f);
    const float search = Md - md;
    const float inv = 1.0f / (float)(SS + 1);
    const float sv = search * inv;
    const float im = fmaf(sv, (float)(s + 1), md);

    const float* ns = nin + s * HW;
    float np[3];
    np[1] = __ldg(ns + pix);
    if (horiz) {
        np[0] = (w > 0)      ? __ldg(ns + pix - 1)  : 0.0f;
        np[2] = (w < WW - 1) ? __ldg(ns + pix + 1)  : 0.0f;
    } else {
        np[0] = (h > 0)      ? __ldg(ns + pix - WW) : 0.0f;
        np[2] = (h < HH - 1) ? __ldg(ns + pix + WW) : 0.0f;
    }

    const float* rowbase = g_bandt + (size_t)h * BAND * WW + w;

    float cost[3], dsv[3];
    #pragma unroll
    for (int c = 0; c < 3; c++) {
        float disp = fmaf(np[c], sv, im);
        dsv[c] = disp;
        float xs = (float)w - disp;
        float x0f = floorf(xs);
        float frac = xs - x0f;
        int b0 = w + 1 - (int)x0f;          // in [1, 73] by construction
        b0 = max(1, min(b0, BAND - 1));     // defensive, normally no-op
        float d0 = __ldg(rowbase + (size_t)b0 * WW);
        float d1 = __ldg(rowbase + (size_t)(b0 - 1) * WW);
        cost[c] = (d0 * (1.0f - frac) + d1 * frac) * (7.0f / 32.0f);
    }

    float m = fmaxf(cost[0], fmaxf(cost[1], cost[2]));
    float e0 = __expf(cost[0] - m);
    float e1 = __expf(cost[1] - m);
    float e2 = __expf(cost[2] - m);
    float rZ = 1.0f / (e0 + e1 + e2);

    nout[s * HW + pix] = (e0 * np[0] + e1 * np[1] + e2 * np[2]) * rZ;
    if (pass == 3)
        disp_out[s * HW + pix] = (e0 * dsv[0] + e1 * dsv[1] + e2 * dsv[2]) * rZ;
}

extern "C" void kernel_launch(void* const* d_in, const int* in_sizes, int n_in,
                              void* d_out, int out_size) {
    const float* left  = (const float*)d_in[0];
    const float* right = (const float*)d_in[1];
    const float* minD  = (const float*)d_in[2];
    const float* maxD  = (const float*)d_in[3];
    const float* noise = (const float*)d_in[4];
    float* disp = (float*)d_out;

    build_table_kernel<<<dim3(2, HH), 192>>>(left, right);
    transpose_band_kernel<<<dim3(4, HH), 256>>>();
    for (int p = 0; p < 4; p++) {
        pm_pass_kernel<<<dim3(4, HH, 3), 256>>>(minD, maxD, noise, disp, p);
    }
}

// round 5
// speedup vs baseline: 1.3354x; 1.1034x over previous
#include <cuda_runtime.h>

#define HH 128
#define WW 256
#define SS 12
#define CC 32
#define BAND 74
#define HW (HH * WW)

// Band pair table: g_band2[(h*BAND + b)*WW + w] = (tab[x0], tab[x0+1]),
// x0 = w+1-b, zero where x out of [0,W). b in [1,73]; row 0 unused.
__device__ float2 g_band2[HH * BAND * WW];       // 19.4 MB
__device__ float g_noiseA[SS * HW];
__device__ float g_noiseB[SS * HW];

#define FMA2(d, a, b, c) \
    asm("fma.rn.f32x2 %0, %1, %2, %3;" : "=l"(d) : "l"(a), "l"(b), "l"(c))
#define PACK2(out, v) \
    asm("mov.b64 %0, {%1, %1};" : "=l"(out) : "r"(__float_as_uint(v)))
#define UNPACK2(lo, hi, in) \
    asm("mov.b64 {%0, %1}, %2;" : "=r"(lo), "=r"(hi) : "l"(in))

// ---------------------------------------------------------------------------
// Fused build: per (row, half-row) 8x8 f32x2 GEMM over the band, staged into
// an smem band buffer (aliases the GEMM tiles), written out as float2 pairs.
// 192 threads = 16 w-tiles x 12 slots (11 band x-tiles used).
// ---------------------------------------------------------------------------
__global__ __launch_bounds__(192) void build_band_kernel(
    const float* __restrict__ left, const float* __restrict__ right) {
    __shared__ float pool[12288];                 // 48 KB
    float (*As)[128] = (float(*)[128])pool;       // 32x128
    float (*Rs)[WW]  = (float(*)[WW])(pool + 4096);
    float (*Sb)[129] = (float(*)[129])pool;       // 74x129 (aliases, post-GEMM)

    const int h = blockIdx.y;
    const int wbase = blockIdx.x * 128;
    const int tid = threadIdx.x;

    for (int i = tid; i < CC * 128; i += 192) {
        int c = i >> 7, wl = i & 127;
        As[c][wl] = left[(c * HH + h) * WW + wbase + wl];
    }
    for (int i = tid; i < CC * WW; i += 192) {
        int c = i >> 8, x = i & 255;
        Rs[c][x] = right[(c * HH + h) * WW + x];
    }
    __syncthreads();

    const int tw = tid / 12;            // w-tile within half-row: 0..15
    const int j  = tid % 12;            // band x-tile slot: 0..10 used
    const int twg = (wbase >> 3) + tw;
    const int txg = twg - 9 + j;        // x-tiles [twg-9, twg+1]
    const bool active = (j < 11) && (txg >= 0) && (txg <= 31);

    const int wl = tw * 8;              // local w base
    const int x  = txg * 8;             // global x base

    unsigned long long acc2[8][4];
    #pragma unroll
    for (int i = 0; i < 8; i++)
        #pragma unroll
        for (int q = 0; q < 4; q++) acc2[i][q] = 0ULL;

    if (active) {
        #pragma unroll 8
        for (int k = 0; k < CC; k++) {
            float a[8];
            *(float4*)&a[0] = *(const float4*)&As[k][wl];
            *(float4*)&a[4] = *(const float4*)&As[k][wl + 4];
            ulonglong2 t0 = *(const ulonglong2*)&Rs[k][x];
            ulonglong2 t1 = *(const ulonglong2*)&Rs[k][x + 4];
            unsigned long long b2[4] = {t0.x, t0.y, t1.x, t1.y};
            #pragma unroll
            for (int i = 0; i < 8; i++) {
                unsigned long long a2;
                PACK2(a2, a[i]);
                #pragma unroll
                for (int q = 0; q < 4; q++)
                    FMA2(acc2[i][q], a2, b2[q], acc2[i][q]);
            }
        }
    }
    __syncthreads();   // GEMM reads done; safe to overwrite pool as Sb

    // Stage accumulators into band layout: Sb[b][w_local], b = w+1-x.
    if (active) {
        const int xl = x - wbase;                // may be negative
        #pragma unroll
        for (int i = 0; i < 8; i++) {
            #pragma unroll
            for (int q = 0; q < 8; q++) {
                unsigned lo, hi;
                UNPACK2(lo, hi, acc2[i][q >> 1]);
                float v = __uint_as_float((q & 1) ? hi : lo);
                int b = wl + i + 1 - xl - q;
                if (b >= 0 && b <= 73) Sb[b][wl + i] = v;
            }
        }
    }
    __syncthreads();

    // Coalesced pair writeout with zero-fill for out-of-image x.
    float2* dst = g_band2 + h * BAND * WW + wbase;
    for (int i2 = tid; i2 < 73 * 128; i2 += 192) {
        int b = (i2 >> 7) + 1;
        int wli = i2 & 127;
        int x0 = wbase + wli + 1 - b;            // x for d0; d1 at x0+1
        float v0 = (x0 >= 0) ? Sb[b][wli] : 0.0f;
        float v1 = (x0 >= -1 && x0 <= 254) ? Sb[b - 1][wli] : 0.0f;
        dst[b * WW + wli] = make_float2(v0, v1);
    }
}

// ---------------------------------------------------------------------------
// One PatchMatch pass. Thread = (pixel, 2 samples). grid=(W/64, H), block=384
// (64 w x 6 sample-groups; thread does samples sg and sg+6).
// ---------------------------------------------------------------------------
__global__ __launch_bounds__(384) void pm_pass_kernel(
    const float* __restrict__ minD, const float* __restrict__ maxD,
    const float* __restrict__ ext_noise, float* __restrict__ disp_out,
    int pass) {
    const int wl = threadIdx.x & 63;
    const int sg = threadIdx.x >> 6;             // 0..5
    const int w  = blockIdx.x * 64 + wl;
    const int h  = blockIdx.y;
    const int pix = h * WW + w;

    const float* nin = (pass == 0) ? ext_noise
                                   : ((pass & 1) ? g_noiseA : g_noiseB);
    float* nout = (pass & 1) ? g_noiseB : g_noiseA;
    const bool horiz = ((pass & 1) == 0);

    const float md = fmaxf(__ldg(minD + pix), 0.0f);
    const float Md = fmaxf(__ldg(maxD + pix), 0.0f);
    const float sv = (Md - md) * (1.0f / (float)(SS + 1));

    const int s0 = sg;                           // samples: sg, sg+6
    const float* ns0 = nin + s0 * HW;

    // --- batch noise loads for both samples (6 independent LDGs) ---
    float np[2][3];
    #pragma unroll
    for (int u = 0; u < 2; u++) {
        const float* ns = ns0 + u * 6 * HW;
        np[u][1] = __ldg(ns + pix);
        if (horiz) {
            np[u][0] = (w > 0)      ? __ldg(ns + pix - 1)  : 0.0f;
            np[u][2] = (w < WW - 1) ? __ldg(ns + pix + 1)  : 0.0f;
        } else {
            np[u][0] = (h > 0)      ? __ldg(ns + pix - WW) : 0.0f;
            np[u][2] = (h < HH - 1) ? __ldg(ns + pix + WW) : 0.0f;
        }
    }

    const float2* brow = g_band2 + h * BAND * WW + w;
    const float fw = (float)w;
    const int wp1 = w + 1;

    // --- 6 independent pair-gathers ---
    float dsv[2][3], frac[2][3];
    float2 dpair[2][3];
    #pragma unroll
    for (int u = 0; u < 2; u++) {
        const float im = fmaf(sv, (float)(s0 + u * 6 + 1), md);
        #pragma unroll
        for (int c = 0; c < 3; c++) {
            float disp = fmaf(np[u][c], sv, im);
            dsv[u][c] = disp;
            float xs = fw - disp;
            int k0 = __float2int_rd(xs);
            frac[u][c] = xs - (float)k0;
            int b0 = wp1 - k0;                   // in [1,73] by construction
            b0 = min(max(b0, 1), BAND - 1);
            dpair[u][c] = __ldg(brow + b0 * WW);
        }
    }

    // --- softmax + outputs ---
    #pragma unroll
    for (int u = 0; u < 2; u++) {
        float e[3];
        #pragma unroll
        for (int c = 0; c < 3; c++) {
            float2 d = dpair[u][c];
            float cost = fmaf(d.y - d.x, frac[u][c], d.x) * (7.0f / 32.0f);
            e[c] = __expf(cost);                 // no max-shift: cost bounded
        }
        float rZ = __fdividef(1.0f, e[0] + e[1] + e[2]);
        int s = s0 + u * 6;
        if (pass == 3) {
            disp_out[s * HW + pix] =
                (e[0] * dsv[u][0] + e[1] * dsv[u][1] + e[2] * dsv[u][2]) * rZ;
        } else {
            nout[s * HW + pix] =
                (e[0] * np[u][0] + e[1] * np[u][1] + e[2] * np[u][2]) * rZ;
        }
    }
}

extern "C" void kernel_launch(void* const* d_in, const int* in_sizes, int n_in,
                              void* d_out, int out_size) {
    const float* left  = (const float*)d_in[0];
    const float* right = (const float*)d_in[1];
    const float* minD  = (const float*)d_in[2];
    const float* maxD  = (const float*)d_in[3];
    const float* noise = (const float*)d_in[4];
    float* disp = (float*)d_out;

    build_band_kernel<<<dim3(2, HH), 192>>>(left, right);
    for (int p = 0; p < 4; p++) {
        pm_pass_kernel<<<dim3(4, HH), 384>>>(minD, maxD, noise, disp, p);
    }
}